// round 1
// baseline (speedup 1.0000x reference)
#include <cuda_runtime.h>

#define VDIM 100000
#define DDIM 128
#define MDIM 200
#define TILE 512
#define NTILE ((VDIM + TILE - 1) / TILE)   // 196

// Scratch state (allocation-free: __device__ globals)
__device__ float g_qd[DDIM];     // current ques_d / o
__device__ float g_aux[MDIM];    // logits accumulator (atomic)
__device__ float g_P[MDIM];      // softmax probabilities
__device__ float g_oacc[DDIM];   // pm @ Wc.T accumulator (atomic)

__device__ __forceinline__ float warp_sum(float v) {
#pragma unroll
    for (int o = 16; o > 0; o >>= 1) v += __shfl_xor_sync(0xffffffffu, v, o);
    return v;
}

__global__ void k_init() {
    int t = threadIdx.x;
    if (t < DDIM) { g_qd[t] = 0.f; g_oacc[t] = 0.f; }
    if (t < MDIM) g_aux[t] = 0.f;
}

// g_qd[d] += sum_v question[v] * Wb[d, v]
__global__ void __launch_bounds__(128) k_quesd(
    const float* __restrict__ vec, const float* __restrict__ W) {
    __shared__ float sv[TILE];
    const int base = blockIdx.x * TILE;
    const int tid = threadIdx.x;
    int v0 = base + tid * 4;
    float4 x = make_float4(0.f, 0.f, 0.f, 0.f);
    if (v0 < VDIM) x = *reinterpret_cast<const float4*>(vec + v0);
    *reinterpret_cast<float4*>(&sv[tid * 4]) = x;
    __syncthreads();
    const int w = tid >> 5, lane = tid & 31;
    for (int d = w; d < DDIM; d += 4) {
        const float* wr = W + (size_t)d * VDIM + base;
        float acc = 0.f;
#pragma unroll
        for (int k = 0; k < 4; k++) {
            int idx = lane * 4 + k * 128;
            if (base + idx < VDIM) {
                float4 wv = *reinterpret_cast<const float4*>(wr + idx);
                float4 s4 = *reinterpret_cast<const float4*>(&sv[idx]);
                acc += wv.x * s4.x + wv.y * s4.y + wv.z * s4.z + wv.w * s4.w;
            }
        }
        acc = warp_sum(acc);
        if (lane == 0) atomicAdd(&g_qd[d], acc);
    }
}

// Fused: s_tile = qd @ Wa[:, tile]  (registers->shared), then
//        g_aux[m] += s_tile . memory[m, tile]
__global__ void __launch_bounds__(128) k_aux(
    const float* __restrict__ Wa, const float* __restrict__ mem) {
    __shared__ float sqd[DDIM];
    __shared__ float ss[TILE];
    const int base = blockIdx.x * TILE;
    const int tid = threadIdx.x;
    if (tid < DDIM) sqd[tid] = g_qd[tid];
    __syncthreads();
    int v0 = base + tid * 4;
    float4 s4 = make_float4(0.f, 0.f, 0.f, 0.f);
    if (v0 < VDIM) {
        const float* wp = Wa + v0;
#pragma unroll 8
        for (int d = 0; d < DDIM; d++) {
            float q = sqd[d];
            float4 a = *reinterpret_cast<const float4*>(wp + (size_t)d * VDIM);
            s4.x += q * a.x; s4.y += q * a.y; s4.z += q * a.z; s4.w += q * a.w;
        }
    }
    *reinterpret_cast<float4*>(&ss[tid * 4]) = s4;
    __syncthreads();
    const int w = tid >> 5, lane = tid & 31;
    for (int m = w; m < MDIM; m += 4) {
        const float* mr = mem + (size_t)m * VDIM + base;
        float acc = 0.f;
#pragma unroll
        for (int k = 0; k < 4; k++) {
            int idx = lane * 4 + k * 128;
            if (base + idx < VDIM) {
                float4 mv = *reinterpret_cast<const float4*>(mr + idx);
                float4 s = *reinterpret_cast<const float4*>(&ss[idx]);
                acc += mv.x * s.x + mv.y * s.y + mv.z * s.z + mv.w * s.w;
            }
        }
        acc = warp_sum(acc);
        if (lane == 0) atomicAdd(&g_aux[m], acc);
    }
}

// logits = g_aux + qd @ temporal_A.T ; P = softmax(logits); reset aux/oacc
__global__ void __launch_bounds__(256) k_soft(const float* __restrict__ tA) {
    __shared__ float sqd[DDIM];
    __shared__ float slog[MDIM];
    __shared__ float red[256];
    const int tid = threadIdx.x;
    if (tid < DDIM) sqd[tid] = g_qd[tid];
    __syncthreads();
    const int w = tid >> 5, lane = tid & 31;
    for (int m = w; m < MDIM; m += 8) {
        float acc = 0.f;
#pragma unroll
        for (int k = 0; k < 4; k++) {
            int d = lane + 32 * k;
            acc += sqd[d] * tA[m * DDIM + d];
        }
        acc = warp_sum(acc);
        if (lane == 0) slog[m] = g_aux[m] + acc;
    }
    __syncthreads();
    red[tid] = (tid < MDIM) ? slog[tid] : -3.0e38f;
    __syncthreads();
    for (int s = 128; s > 0; s >>= 1) {
        if (tid < s) red[tid] = fmaxf(red[tid], red[tid + s]);
        __syncthreads();
    }
    float mx = red[0];
    __syncthreads();
    float e = 0.f;
    if (tid < MDIM) e = __expf(slog[tid] - mx);
    red[tid] = e;
    __syncthreads();
    for (int s = 128; s > 0; s >>= 1) {
        if (tid < s) red[tid] += red[tid + s];
        __syncthreads();
    }
    float inv = 1.f / red[0];
    if (tid < MDIM) { g_P[tid] = e * inv; g_aux[tid] = 0.f; }
    if (tid < DDIM) g_oacc[tid] = 0.f;
}

// Fused: pm_tile = P.T @ memory[:, tile] (pruned: P is near one-hot), then
//        g_oacc[d] += pm_tile . Wc[d, tile]
__global__ void __launch_bounds__(128) k_o(
    const float* __restrict__ mem, const float* __restrict__ Wc) {
    __shared__ float sP[MDIM];
    __shared__ float spm[TILE];
    const int base = blockIdx.x * TILE;
    const int tid = threadIdx.x;
    for (int i = tid; i < MDIM; i += 128) sP[i] = g_P[i];
    __syncthreads();
    int v0 = base + tid * 4;
    float4 pm = make_float4(0.f, 0.f, 0.f, 0.f);
    if (v0 < VDIM) {
        const float* mp = mem + v0;
        for (int m = 0; m < MDIM; m++) {
            float p = sP[m];
            if (p > 1e-10f) {  // softmax is ~one-hot; dropped mass < 2e-8
                float4 mv = *reinterpret_cast<const float4*>(mp + (size_t)m * VDIM);
                pm.x += p * mv.x; pm.y += p * mv.y; pm.z += p * mv.z; pm.w += p * mv.w;
            }
        }
    }
    *reinterpret_cast<float4*>(&spm[tid * 4]) = pm;
    __syncthreads();
    const int w = tid >> 5, lane = tid & 31;
    for (int d = w; d < DDIM; d += 4) {
        const float* wr = Wc + (size_t)d * VDIM + base;
        float acc = 0.f;
#pragma unroll
        for (int k = 0; k < 4; k++) {
            int idx = lane * 4 + k * 128;
            if (base + idx < VDIM) {
                float4 wv = *reinterpret_cast<const float4*>(wr + idx);
                float4 pv = *reinterpret_cast<const float4*>(&spm[idx]);
                acc += wv.x * pv.x + wv.y * pv.y + wv.z * pv.z + wv.w * pv.w;
            }
        }
        acc = warp_sum(acc);
        if (lane == 0) atomicAdd(&g_oacc[d], acc);
    }
}

// qd[d] = oacc[d] + sum_m P[m]*tC[m,d] + qd[d]
__global__ void __launch_bounds__(128) k_epi(const float* __restrict__ tC) {
    __shared__ float sP[MDIM];
    const int tid = threadIdx.x;
    for (int i = tid; i < MDIM; i += 128) sP[i] = g_P[i];
    __syncthreads();
    float acc = g_oacc[tid] + g_qd[tid];
    for (int m = 0; m < MDIM; m++) acc += sP[m] * tC[m * DDIM + tid];
    g_qd[tid] = acc;
}

// out[v] = sum_d qd[d] * Wout[v, d]  (warp per row)
__global__ void __launch_bounds__(256) k_out(
    const float* __restrict__ Wout, float* __restrict__ out) {
    const int lane = threadIdx.x & 31;
    const int gw = (blockIdx.x * blockDim.x + threadIdx.x) >> 5;
    const int nw = (gridDim.x * blockDim.x) >> 5;
    float4 q = *reinterpret_cast<const float4*>(&g_qd[lane * 4]);
    for (int v = gw; v < VDIM; v += nw) {
        float4 wv = *reinterpret_cast<const float4*>(Wout + (size_t)v * DDIM + lane * 4);
        float acc = q.x * wv.x + q.y * wv.y + q.z * wv.z + q.w * wv.w;
        acc = warp_sum(acc);
        if (lane == 0) out[v] = acc;
    }
}

extern "C" void kernel_launch(void* const* d_in, const int* in_sizes, int n_in,
                              void* d_out, int out_size) {
    const float* question = (const float*)d_in[0];
    const float* memory   = (const float*)d_in[1];
    const float* Wa       = (const float*)d_in[2];
    const float* Wb       = (const float*)d_in[3];
    const float* Wc       = (const float*)d_in[4];
    const float* Wout     = (const float*)d_in[5];
    const float* tA       = (const float*)d_in[6];
    const float* tC       = (const float*)d_in[7];
    float* out = (float*)d_out;

    k_init<<<1, 256>>>();
    k_quesd<<<NTILE, 128>>>(question, Wb);
    for (int h = 0; h < 3; h++) {
        k_aux<<<NTILE, 128>>>(Wa, memory);
        k_soft<<<1, 256>>>(tA);
        k_o<<<NTILE, 128>>>(memory, Wc);
        k_epi<<<1, 128>>>(tC);
    }
    k_out<<<416, 256>>>(Wout, out);
}

// round 4
// speedup vs baseline: 1.3727x; 1.3727x over previous
#include <cuda_runtime.h>

#define VV 100000
#define DD 128
#define MM 200
#define HOPS 3
#define SS 256
#define NSTRIP ((VV + SS - 1) / SS)   // 391 (tail 160)
#define PTHR 1e-10f

// ---------------- scratch (allocation-free) ----------------
__device__ float g_qd[DD];             // current ques_d / o
__device__ float g_logit[HOPS][MM];    // full logits (mem part + tA part), atomic
__device__ float g_oacc[HOPS][DD];     // Wc @ pm, atomic
__device__ float g_pw[MM];             // active softmax weights
__device__ int   g_act[MM];            // active slot indices
__device__ int   g_nact;

__device__ __forceinline__ float warp_sum(float v) {
#pragma unroll
    for (int o = 16; o > 0; o >>= 1) v += __shfl_xor_sync(0xffffffffu, v, o);
    return v;
}

__global__ void k_init() {
    int t = threadIdx.x;
    if (t < DD) g_qd[t] = 0.f;
    if (t < HOPS * MM) ((float*)g_logit)[t] = 0.f;
    if (t < HOPS * DD) ((float*)g_oacc)[t] = 0.f;
}

// g_qd[r] += Wb[r] . question   — unit u = (row, half of V)
__global__ void __launch_bounds__(256) k_quesd(
    const float* __restrict__ Wb, const float* __restrict__ question) {
    __shared__ float sred[8];
    const int tid = threadIdx.x, lane = tid & 31, w = tid >> 5;
    const int r = blockIdx.x >> 1, half = blockIdx.x & 1;
    const float4* wr = (const float4*)(Wb + (size_t)r * VV + half * 50000);
    const float4* qv = (const float4*)(question + half * 50000);
    float acc = 0.f;
    for (int q = tid; q < 12500; q += 256) {
        float4 a = wr[q], b = qv[q];
        acc += a.x * b.x + a.y * b.y + a.z * b.z + a.w * b.w;
    }
    acc = warp_sum(acc);
    if (lane == 0) sred[w] = acc;
    __syncthreads();
    if (w == 0) {
        float x = (lane < 8) ? sred[lane] : 0.f;
        x = warp_sum(x);
        if (lane == 0) atomicAdd(&g_qd[r], x);
    }
}

// Fused: per strip, s = qd@Wa[:,strip] then logit[m] += s . mem[m,strip].
// Units >= NSTRIP compute the tA part of the logits.
__global__ void __launch_bounds__(512) k_aux(
    const float* __restrict__ Wa, const float* __restrict__ memory,
    const float* __restrict__ tA, int hop) {
    __shared__ __align__(16) float sqd[DD];
    __shared__ __align__(16) float ss[SS];
    const int tid = threadIdx.x, lane = tid & 31, w = tid >> 5;
    if (tid < DD) sqd[tid] = g_qd[tid];
    __syncthreads();

    int u = blockIdx.x;
    if (u < NSTRIP) {
        const int base = u * SS;
        const int len = (VV - base < SS) ? (VV - base) : SS;
        const int c = tid & (SS - 1);
        const int half = tid >> 8;               // d in [half*64, half*64+64)
        float acc = 0.f;
        if (c < len) {
            const float* wp = Wa + (size_t)(half * 64) * VV + base + c;
#pragma unroll 16
            for (int d = 0; d < 64; d++)
                acc += sqd[half * 64 + d] * wp[(size_t)d * VV];
        }
        if (half == 0) ss[c] = acc;              // zero for c>=len
        __syncthreads();
        if (half == 1 && c < len) ss[c] += acc;
        __syncthreads();

        const float4* sf = (const float4*)ss;
        for (int m = w; m < MM; m += 16) {
            const float4* mr = (const float4*)(memory + (size_t)m * VV + base);
            float a = 0.f;
            if (lane * 4 < len) {
                float4 mv = mr[lane], sv = sf[lane];
                a += mv.x * sv.x + mv.y * sv.y + mv.z * sv.z + mv.w * sv.w;
            }
            if ((lane + 32) * 4 < len) {
                float4 mv = mr[lane + 32], sv = sf[lane + 32];
                a += mv.x * sv.x + mv.y * sv.y + mv.z * sv.z + mv.w * sv.w;
            }
            a = warp_sum(a);
            if (lane == 0) atomicAdd(&g_logit[hop][m], a);
        }
    } else {
        // tA part: chunk of 25 m-rows; logit[m] += qd . tA[m]
        const int chunk = u - NSTRIP;            // 0..7
        for (int m = chunk * 25 + w; m < chunk * 25 + 25 && m < MM; m += 16) {
            float a = 0.f;
#pragma unroll
            for (int k = 0; k < 4; k++) {
                int d = lane + 32 * k;
                a += sqd[d] * tA[m * DD + d];
            }
            a = warp_sum(a);
            if (lane == 0) atomicAdd(&g_logit[hop][m], a);
        }
    }
}

// P = softmax(logit[hop]); emit pruned active list. 1 block, tiny reads.
__global__ void __launch_bounds__(256) k_psoft(int hop) {
    __shared__ float sl[MM];
    __shared__ float sred[256];
    __shared__ int sn;
    const int tid = threadIdx.x;
    if (tid < MM) sl[tid] = g_logit[hop][tid];
    if (tid == 0) sn = 0;
    __syncthreads();
    sred[tid] = (tid < MM) ? sl[tid] : -3.4e38f;
    __syncthreads();
    for (int s = 128; s >= 1; s >>= 1) {
        if (tid < s) sred[tid] = fmaxf(sred[tid], sred[tid + s]);
        __syncthreads();
    }
    float mx = sred[0];
    __syncthreads();
    float e = (tid < MM) ? __expf(sl[tid] - mx) : 0.f;
    sred[tid] = e;
    __syncthreads();
    for (int s = 128; s >= 1; s >>= 1) {
        if (tid < s) sred[tid] += sred[tid + s];
        __syncthreads();
    }
    float inv = 1.f / sred[0];
    __syncthreads();
    float p = e * inv;
    if (tid < MM && p > PTHR) {
        int i = atomicAdd(&sn, 1);
        g_act[i] = tid;
        g_pw[i] = p;
    }
    __syncthreads();
    if (tid == 0) g_nact = sn;
}

// Fused: per strip, pm = sum_act p*mem[act,strip] then oacc[d] += pm . Wc[d,strip]
__global__ void __launch_bounds__(512) k_po(
    const float* __restrict__ memory, const float* __restrict__ Wc, int hop) {
    __shared__ __align__(16) float ss[SS];
    __shared__ float spw[MM];
    __shared__ int sact[MM];
    __shared__ int sna;
    const int tid = threadIdx.x, lane = tid & 31, w = tid >> 5;
    if (tid == 0) sna = g_nact;
    __syncthreads();
    const int na = sna;
    if (tid < na) { spw[tid] = g_pw[tid]; sact[tid] = g_act[tid]; }
    __syncthreads();

    const int base = blockIdx.x * SS;
    const int len = (VV - base < SS) ? (VV - base) : SS;
    if (tid < SS) {
        float a = 0.f;
        if (tid < len) {
            for (int i = 0; i < na; i++)
                a += spw[i] * memory[(size_t)sact[i] * VV + base + tid];
        }
        ss[tid] = a;
    }
    __syncthreads();

    const float4* sf = (const float4*)ss;
    for (int d = w; d < DD; d += 16) {
        const float4* wr = (const float4*)(Wc + (size_t)d * VV + base);
        float a = 0.f;
        if (lane * 4 < len) {
            float4 wv = wr[lane], sv = sf[lane];
            a += wv.x * sv.x + wv.y * sv.y + wv.z * sv.z + wv.w * sv.w;
        }
        if ((lane + 32) * 4 < len) {
            float4 wv = wr[lane + 32], sv = sf[lane + 32];
            a += wv.x * sv.x + wv.y * sv.y + wv.z * sv.z + wv.w * sv.w;
        }
        a = warp_sum(a);
        if (lane == 0) atomicAdd(&g_oacc[hop][d], a);
    }
}

// qd[d] += oacc[hop][d] + sum_act p * tC[act][d]   (1 block, ~1KB reads)
__global__ void __launch_bounds__(128) k_epi(const float* __restrict__ tC, int hop) {
    const int d = threadIdx.x;
    const int na = g_nact;
    float acc = g_qd[d] + g_oacc[hop][d];
    for (int i = 0; i < na; i++)
        acc += g_pw[i] * tC[g_act[i] * DD + d];
    g_qd[d] = acc;
}

// out[v] = qd . Wout[v]   (warp per row, grid-stride)
__global__ void __launch_bounds__(256) k_out(
    const float* __restrict__ Wout, float* __restrict__ out) {
    const int lane = threadIdx.x & 31;
    const int gw = (blockIdx.x * 256 + threadIdx.x) >> 5;
    const int nw = (gridDim.x * 256) >> 5;
    float4 qv = *(const float4*)(&g_qd[lane * 4]);
    for (int r = gw; r < VV; r += nw) {
        float4 wv = ((const float4*)(Wout + (size_t)r * DD))[lane];
        float acc = qv.x * wv.x + qv.y * wv.y + qv.z * wv.z + qv.w * wv.w;
        acc = warp_sum(acc);
        if (lane == 0) out[r] = acc;
    }
}

extern "C" void kernel_launch(void* const* d_in, const int* in_sizes, int n_in,
                              void* d_out, int out_size) {
    const float* question = (const float*)d_in[0];
    const float* memory   = (const float*)d_in[1];
    const float* Wa       = (const float*)d_in[2];
    const float* Wb       = (const float*)d_in[3];
    const float* Wc       = (const float*)d_in[4];
    const float* Wout     = (const float*)d_in[5];
    const float* tA       = (const float*)d_in[6];
    const float* tC       = (const float*)d_in[7];
    float* out = (float*)d_out;

    k_init<<<1, 1024>>>();
    k_quesd<<<DD * 2, 256>>>(Wb, question);
    for (int h = 0; h < HOPS; h++) {
        k_aux<<<NSTRIP + 8, 512>>>(Wa, memory, tA, h);
        k_psoft<<<1, 256>>>(h);
        k_po<<<NSTRIP, 512>>>(memory, Wc, h);
        k_epi<<<1, 128>>>(tC, h);
    }
    k_out<<<592, 256>>>(Wout, out);
}